// round 15
// baseline (speedup 1.0000x reference)
#include <cuda_runtime.h>
#include <math.h>
#include <stdint.h>

// Problem constants (fixed by setup_inputs)
#define HH 512
#define WW 512
#define HW (HH * WW)            // 262144
#define VV 64
#define V3 (VV * VV * VV)       // 262144
#define NB 32

// Reachability: d>0 && in-range forces cz = rint((d+2)*15.75) in [32,63].
// Scratch holds ONE QUARTER (8 batches): [bl][((cx*64+cy)*32 + (cz-32))]
// float4{count,r,g,b} = 16 MB, reused 4x per call.
//
// Zeroing is FREE: finalize rezeros every line it reads (L2-hit stores that
// hide under its DRAM writes). Scratch is zero at call start (load-time init
// on call 1, fin_Q3's rezero afterwards) and zero again at call end.
// Eviction-safe: any dirty line (partial sums or zeros) written back to DRAM
// is simply refetched with its correct value - no discard, no retention
// assumption.
#define SCR_PER_B (VV * VV * 32)     // 131072 (= 1<<17) entries per batch
#define QB 8                         // batches per quarter
#define SCR_Q (QB * SCR_PER_B)       // 1048576 entries = 16 MB

__device__ __align__(128) float4 g_acc[SCR_Q];

// ---- helpers ---------------------------------------------------------------
__device__ __forceinline__ uint64_t pol_evict_first() {
    uint64_t p;
    asm("createpolicy.fractional.L2::evict_first.b64 %0, 1.0;" : "=l"(p));
    return p;
}
__device__ __forceinline__ float4 ldg_stream(const float* a, uint64_t pol) {
    float4 v;
    asm("ld.global.nc.L2::cache_hint.v4.f32 {%0,%1,%2,%3}, [%4], %5;"
        : "=f"(v.x), "=f"(v.y), "=f"(v.z), "=f"(v.w) : "l"(a), "l"(pol));
    return v;
}
__device__ __forceinline__ void ldg256(const float* p, float4& v0, float4& v1) {
    asm volatile("ld.global.v8.f32 {%0,%1,%2,%3,%4,%5,%6,%7}, [%8];"
                 : "=f"(v0.x), "=f"(v0.y), "=f"(v0.z), "=f"(v0.w),
                   "=f"(v1.x), "=f"(v1.y), "=f"(v1.z), "=f"(v1.w)
                 : "l"(p));
}
__device__ __forceinline__ void stg256(float* p, float4 v0, float4 v1) {
    asm volatile("st.global.v8.f32 [%0], {%1,%2,%3,%4,%5,%6,%7,%8};"
                 :: "l"(p), "f"(v0.x), "f"(v0.y), "f"(v0.z), "f"(v0.w),
                    "f"(v1.x), "f"(v1.y), "f"(v1.z), "f"(v1.w)
                 : "memory");
}
__device__ __forceinline__ void stg256_hint(float* p, float4 v0, float4 v1,
                                            uint64_t pol) {
    asm volatile("st.global.L2::cache_hint.v8.f32 [%0], "
                 "{%1,%2,%3,%4,%5,%6,%7,%8}, %9;"
                 :: "l"(p), "f"(v0.x), "f"(v0.y), "f"(v0.z), "f"(v0.w),
                    "f"(v1.x), "f"(v1.y), "f"(v1.z), "f"(v1.w), "l"(pol)
                 : "memory");
}

// --------------------------------------------------------------- splat ----
// One quarter (8 batches starting at b0). Scratch index uses the LOCAL batch.
__global__ __launch_bounds__(256) void splat_kernel(
        const float* __restrict__ rgbd, int b0) {
    int t = blockIdx.x * blockDim.x + threadIdx.x;   // 524288 threads
    uint64_t pfirst = pol_evict_first();

    int idx = t << 2;                // first of 4 consecutive pixels (local)
    int bl = idx >> 18;              // batch within quarter (0..7)
    int p = idx & (HW - 1);          // pixel in image (mult of 4)
    int h = p >> 9;
    int w0 = p & (WW - 1);

    const float* base = rgbd + (size_t)(b0 + bl) * (4 * HW);
    float4 d4 = ldg_stream(base + 3 * HW + p, pfirst);

    float dv[4] = {d4.x, d4.y, d4.z, d4.w};
    int   lin[4];
    bool  valid[4];
    bool  any = false;
    float yb = (float)h - 256.0f;    // fx=fy=256, cx=cy=256

    #pragma unroll
    for (int k = 0; k < 4; k++) {
        float d = dv[k];
        bool ok = (d > 0.0f) && (d < 10.0f) && isfinite(d);
        float x = ((float)(w0 + k) - 256.0f) * d * (1.0f / 256.0f);
        float y = yb * d * (1.0f / 256.0f);
        // rintf = round-half-even = jnp.round; 15.75 == 63/4 exactly, same
        // single rounding as ((p+2)/4)*63 in the reference.
        float fx_ = rintf((x + 2.0f) * 15.75f);
        float fy_ = rintf((y + 2.0f) * 15.75f);
        float fz_ = rintf((d + 2.0f) * 15.75f);
        ok = ok && (fx_ >= 0.0f) && (fx_ <= 63.0f)
                && (fy_ >= 0.0f) && (fy_ <= 63.0f)
                && (fz_ >= 32.0f) && (fz_ <= 63.0f);
        valid[k] = ok;
        any = any || ok;
        int cx = (int)fx_, cy = (int)fy_, cz = (int)fz_;
        lin[k] = (bl << 17) + ((((cx << 6) | cy) << 5) | (cz - 32));
    }

    if (!any) return;

    float4 r4 = ldg_stream(base + 0 * HW + p, pfirst);
    float4 g4 = ldg_stream(base + 1 * HW + p, pfirst);
    float4 b4 = ldg_stream(base + 2 * HW + p, pfirst);
    float rv[4] = {r4.x, r4.y, r4.z, r4.w};
    float gv[4] = {g4.x, g4.y, g4.z, g4.w};
    float bv[4] = {b4.x, b4.y, b4.z, b4.w};

    #pragma unroll
    for (int k = 0; k < 4; k++) {
        if (valid[k]) {
            float* a = (float*)&g_acc[lin[k]];
            asm volatile("red.global.add.v4.f32 [%0], {%1,%2,%3,%4};"
                         :: "l"(a), "f"(1.0f), "f"(rv[k]), "f"(gv[k]),
                            "f"(bv[k]) : "memory");
        }
    }
}

// ------------------------------------------------------------ finalize ----
// Branch-free resolve: count==0 => sums exactly 0 => sum*rcp(max(count,1))==0.
__device__ __forceinline__ void resolve(float4 a, float& occ, float& r,
                                        float& g, float& b) {
    float inv;
    asm("rcp.approx.f32 %0, %1;" : "=f"(inv) : "f"(fmaxf(a.x, 1.0f)));
    occ = (a.x > 0.0f) ? 1.0f : 0.0f;
    r = a.y * inv;
    g = a.z * inv;
    b = a.w * inv;
}

// One quarter. Thread t owns ONE 128B scratch line (8 entries): 4 x LDG.256
// in, REZERO the line (L2-hit stores -> free zeroing for the next quarter /
// next call), 8 x STG.256 of output (occupied + constant-zero halves).
__global__ __launch_bounds__(256) void finalize_kernel(
        float* __restrict__ out, int b0) {
    int t = blockIdx.x * blockDim.x + threadIdx.x;   // SCR_Q/8 threads
    uint64_t pfirst = pol_evict_first();

    int s = t << 3;                    // 8 contiguous entries (one 128B line)
    int bl = s >> 17;                  // batch within quarter
    int sl = s & (SCR_PER_B - 1);      // ((cx*64+cy)*32 + (cz-32)), mult of 8

    float* sp = (float*)&g_acc[s];
    float4 a[8];
    ldg256(sp,      a[0], a[1]);
    ldg256(sp + 8,  a[2], a[3]);
    ldg256(sp + 16, a[4], a[5]);
    ldg256(sp + 24, a[6], a[7]);

    // Rezero the line immediately (values already in registers). These are
    // L2-hit stores; they keep the zero invariant for the next quarter and
    // the next graph replay, and are eviction-safe by construction.
    float4 z = make_float4(0.f, 0.f, 0.f, 0.f);
    stg256(sp,      z, z);
    stg256(sp + 8,  z, z);
    stg256(sp + 16, z, z);
    stg256(sp + 24, z, z);

    float4 occ0, rr0, gg0, bb0, occ1, rr1, gg1, bb1;
    resolve(a[0], occ0.x, rr0.x, gg0.x, bb0.x);
    resolve(a[1], occ0.y, rr0.y, gg0.y, bb0.y);
    resolve(a[2], occ0.z, rr0.z, gg0.z, bb0.z);
    resolve(a[3], occ0.w, rr0.w, gg0.w, bb0.w);
    resolve(a[4], occ1.x, rr1.x, gg1.x, bb1.x);
    resolve(a[5], occ1.y, rr1.y, gg1.y, bb1.y);
    resolve(a[6], occ1.z, rr1.z, gg1.z, bb1.z);
    resolve(a[7], occ1.w, rr1.w, gg1.w, bb1.w);

    int rhi = (sl >> 5) << 6;          // (cx*64+cy)*64
    int rocc = rhi + (sl & 31) + 32;   // occupied half (32B aligned)
    int rzer = rhi + (sl & 31);        // zero half (32B aligned)
    float* ob = out + (size_t)(b0 + bl) * (4 * V3);

    stg256_hint(ob + rocc,          occ0, occ1, pfirst);
    stg256_hint(ob + V3 + rocc,     rr0,  rr1,  pfirst);
    stg256_hint(ob + 2 * V3 + rocc, gg0,  gg1,  pfirst);
    stg256_hint(ob + 3 * V3 + rocc, bb0,  bb1,  pfirst);

    stg256_hint(ob + rzer,          z, z, pfirst);
    stg256_hint(ob + V3 + rzer,     z, z, pfirst);
    stg256_hint(ob + 2 * V3 + rzer, z, z, pfirst);
    stg256_hint(ob + 3 * V3 + rzer, z, z, pfirst);
}

extern "C" void kernel_launch(void* const* d_in, const int* in_sizes, int n_in,
                              void* d_out, int out_size) {
    const float* rgbd = (const float*)d_in[0];
    float* out = (float*)d_out;

    const int T = 256;
    const int SPLAT_CTAS = (QB * HW / 4) / T;   // 2048
    const int FIN_CTAS = (SCR_Q / 8) / T;       // 512

    #pragma unroll
    for (int q = 0; q < 4; q++) {
        splat_kernel<<<SPLAT_CTAS, T>>>(rgbd, q * QB);
        finalize_kernel<<<FIN_CTAS, T>>>(out, q * QB);
    }
}